// round 7
// baseline (speedup 1.0000x reference)
#include <cuda_runtime.h>
#include <cuda_bf16.h>
#include <math.h>
#include <stdint.h>

// expm(S) for 4096 skew-symmetric 64x64 matrices.
// Scaling & squaring (s=4), degree-9 Paterson-Stockmeyer, 9 matmuls of 64^3.
// GEMMs: mma.sync.m16n8k16 bf16 split hi/lo (3 products), fp32 accumulate.
// TWO matrices per CTA, software-pipelined: each phase issues the mainloop of
// one matrix first, then the (independent) register epilogue of the other.
// One barrier per phase. Double accumulator sets.

#define LDO 136     // operand pitch in bf16 elems (272 B -> conflict-free LDSM)
#define SBP 66      // fp32 skew-matrix pitch

#define SM_A   0        // A operand: 64 rows x [hi 64 | lo 64] bf16 -> 17408 B
#define SM_B   17408    // B operand: row n = R^T row n, [hi|lo]    -> 17408 B
#define SM_SB  34816    // fp32 skew matrix, pitch 66 -> 16896 B
#define SLOT   51712    // bytes per matrix slot
#define SMEM_BYTES (2 * SLOT)

static __device__ __forceinline__ uint32_t smem_u32(const void* p) {
    uint32_t a;
    asm("{ .reg .u64 t; cvta.to.shared.u64 t, %1; cvt.u32.u64 %0, t; }" : "=r"(a) : "l"(p));
    return a;
}
static __device__ __forceinline__ void ldsm4(uint32_t* r, uint32_t a) {
    asm volatile("ldmatrix.sync.aligned.m8n8.x4.shared.b16 {%0,%1,%2,%3}, [%4];"
        : "=r"(r[0]), "=r"(r[1]), "=r"(r[2]), "=r"(r[3]) : "r"(a));
}
static __device__ __forceinline__ void mma16816(float* c, const uint32_t* a, const uint32_t* b) {
    asm volatile("mma.sync.aligned.m16n8k16.row.col.f32.bf16.bf16.f32 "
        "{%0,%1,%2,%3}, {%4,%5,%6,%7}, {%8,%9}, {%0,%1,%2,%3};"
        : "+f"(c[0]), "+f"(c[1]), "+f"(c[2]), "+f"(c[3])
        : "r"(a[0]), "r"(a[1]), "r"(a[2]), "r"(a[3]), "r"(b[0]), "r"(b[1]));
}
static __device__ __forceinline__ uint32_t mov_t(uint32_t s) {
    uint32_t d;
    asm("movmatrix.sync.aligned.m8n8.trans.b16 %0, %1;" : "=r"(d) : "r"(s));
    return d;
}
// hw = {bf16(x1)<<16 | bf16(x0)}, lw = residual pair, via packed cvt
static __device__ __forceinline__ void splitw(float x0, float x1, uint32_t& hw, uint32_t& lw) {
    asm("cvt.rn.bf16x2.f32 %0, %1, %2;" : "=r"(hw) : "f"(x1), "f"(x0));
    float h0 = __uint_as_float(hw << 16);
    float h1 = __uint_as_float(hw & 0xffff0000u);
    float r0 = x0 - h0, r1 = x1 - h1;
    asm("cvt.rn.bf16x2.f32 %0, %1, %2;" : "=r"(lw) : "f"(r1), "f"(r0));
}

// Warp quadrant mainloop: base = smem u32 addr of this matrix's slot.
static __device__ __forceinline__ void mm_compute(float c[2][4][4], uint32_t base, int wid, int lid) {
#pragma unroll
    for (int m = 0; m < 2; m++)
#pragma unroll
        for (int j = 0; j < 4; j++)
#pragma unroll
            for (int q = 0; q < 4; q++) c[m][j][q] = 0.f;

    const int r0 = (wid >> 1) * 32, c0 = (wid & 1) * 32;
    const uint32_t aA = base + SM_A + (uint32_t)((r0 + (lid & 15)) * LDO + (lid >> 4) * 8) * 2;
    const int brow = (lid & 7) + ((lid & 16) ? 8 : 0);
    const int bcol = (lid & 8) ? 8 : 0;
    const uint32_t bA = base + SM_B + (uint32_t)((c0 + brow) * LDO + bcol) * 2;
    const uint32_t rstep = 16 * LDO * 2;

#pragma unroll
    for (int kt = 0; kt < 4; kt++) {
        const uint32_t ko = (uint32_t)kt * 32;
        uint32_t ah[2][4], bh[2][4];
        ldsm4(ah[0], aA + ko);
        ldsm4(ah[1], aA + rstep + ko);
        ldsm4(bh[0], bA + ko);
        ldsm4(bh[1], bA + rstep + ko);
#pragma unroll
        for (int m = 0; m < 2; m++)
#pragma unroll
            for (int n = 0; n < 2; n++) {
                mma16816(c[m][2 * n],     ah[m], bh[n]);
                mma16816(c[m][2 * n + 1], ah[m], bh[n] + 2);
            }
        {
            uint32_t bl[2][4];
            ldsm4(bl[0], bA + 128 + ko);
            ldsm4(bl[1], bA + rstep + 128 + ko);
#pragma unroll
            for (int m = 0; m < 2; m++)
#pragma unroll
                for (int n = 0; n < 2; n++) {
                    mma16816(c[m][2 * n],     ah[m], bl[n]);
                    mma16816(c[m][2 * n + 1], ah[m], bl[n] + 2);
                }
        }
        {
            uint32_t al[2][4];
            ldsm4(al[0], aA + 128 + ko);
            ldsm4(al[1], aA + rstep + 128 + ko);
#pragma unroll
            for (int m = 0; m < 2; m++)
#pragma unroll
                for (int n = 0; n < 2; n++) {
                    mma16816(c[m][2 * n],     al[m], bh[n]);
                    mma16816(c[m][2 * n + 1], al[m], bh[n] + 2);
                }
        }
    }
}

// Register epilogue for one matrix slot.
template <bool WA, bool WB, bool LIN, bool GM>
static __device__ __forceinline__ void epilogue(
    float c[2][4][4], char* slot, float* gout, int wid, int lid, float aI, float bB)
{
    __nv_bfloat16* Abuf = reinterpret_cast<__nv_bfloat16*>(slot + SM_A);
    __nv_bfloat16* Bbuf = reinterpret_cast<__nv_bfloat16*>(slot + SM_B);
    const float* sB = reinterpret_cast<const float*>(slot + SM_SB);
    const int g = lid >> 2, tg = lid & 3;
    const int r0 = (wid >> 1) * 32, c0 = (wid & 1) * 32;
#pragma unroll
    for (int m = 0; m < 2; m++) {
#pragma unroll
        for (int j = 0; j < 4; j++) {
            const int col = c0 + 8 * j + 2 * tg;
#pragma unroll
            for (int h = 0; h < 2; h++) {
                const int row = r0 + 16 * m + 8 * h + g;
                float x0 = c[m][j][2 * h], x1 = c[m][j][2 * h + 1];
                if (LIN) {
                    float2 bv = *reinterpret_cast<const float2*>(sB + row * SBP + col);
                    x0 += bB * bv.x;
                    x1 += bB * bv.y;
                    if (col == row) x0 += aI;
                    if (col + 1 == row) x1 += aI;
                }
                if (GM) {
                    *reinterpret_cast<float2*>(gout + row * 64 + col) = make_float2(x0, x1);
                } else {
                    uint32_t hw, lw;
                    splitw(x0, x1, hw, lw);
                    if (WA) {
                        *reinterpret_cast<uint32_t*>(Abuf + row * LDO + col) = hw;
                        *reinterpret_cast<uint32_t*>(Abuf + row * LDO + 64 + col) = lw;
                    }
                    if (WB) {
                        uint32_t hwT = mov_t(hw), lwT = mov_t(lw);
                        const int trow = c0 + 8 * j + g;
                        const int tcol = r0 + 16 * m + 8 * h + 2 * tg;
                        *reinterpret_cast<uint32_t*>(Bbuf + trow * LDO + tcol) = hwT;
                        *reinterpret_cast<uint32_t*>(Bbuf + trow * LDO + 64 + tcol) = lwT;
                    }
                }
            }
        }
    }
}

// Step-k epilogue dispatch for one matrix (k = 0..8).
static __device__ __forceinline__ void epi_dispatch(
    int k, float c[2][4][4], char* slot, float* gout, int tid, int wid, int lid)
{
    const float A3 = 1.3888889e-3f, B3 = 1.9841270e-4f;
    const float A2 = 4.1666668e-2f, B2c = 8.3333333e-3f;
    const float A1 = 0.5f, B1 = 1.6666667e-1f;

    if (k == 0) {
        // Abuf <- B2; Bbuf <- r4^T = A4*I - B4*B
        epilogue<true, false, false, false>(c, slot, nullptr, wid, lid, 0.f, 0.f);
        const float A4 = 2.4801587e-5f, B4 = 2.7557319e-6f;
        __nv_bfloat16* Bbuf = reinterpret_cast<__nv_bfloat16*>(slot + SM_B);
        const float* sB = reinterpret_cast<const float*>(slot + SM_SB);
        const int n = tid >> 1;
        const int k0 = (tid & 1) * 32;
#pragma unroll 8
        for (int kk = k0; kk < k0 + 32; kk += 2) {
            float x0 = -B4 * sB[n * SBP + kk] + (kk == n ? A4 : 0.f);
            float x1 = -B4 * sB[n * SBP + kk + 1] + (kk + 1 == n ? A4 : 0.f);
            uint32_t hw, lw;
            splitw(x0, x1, hw, lw);
            *reinterpret_cast<uint32_t*>(Bbuf + n * LDO + kk) = hw;
            *reinterpret_cast<uint32_t*>(Bbuf + n * LDO + 64 + kk) = lw;
        }
    } else if (k <= 3) {
        float a = (k == 1) ? A3 : (k == 2) ? A2 : A1;
        float b = (k == 1) ? B3 : (k == 2) ? B2c : B1;
        epilogue<false, true, true, false>(c, slot, nullptr, wid, lid, a, b);
    } else if (k == 4) {
        epilogue<true, true, true, false>(c, slot, nullptr, wid, lid, 1.f, 1.f);
    } else if (k < 8) {
        epilogue<true, true, false, false>(c, slot, nullptr, wid, lid, 0.f, 0.f);
    } else {
        epilogue<false, false, false, true>(c, slot, gout, wid, lid, 0.f, 0.f);
    }
}

__global__ void __launch_bounds__(128, 2)
SkewSymMatrixExp_kernel(const float* __restrict__ Svec, float* __restrict__ out)
{
    extern __shared__ char smem[];
    const uint32_t sb = smem_u32(smem);
    const int tid = threadIdx.x, wid = tid >> 5, lid = tid & 31;

    // ---- prologue: scatter + initial operands for BOTH matrices
#pragma unroll 1
    for (int m = 0; m < 2; m++) {
        char* slot = smem + m * SLOT;
        float* sB = reinterpret_cast<float*>(slot + SM_SB);
        const float* v = Svec + (size_t)(2 * blockIdx.x + m) * 2016;

        if (tid < 64) sB[tid * SBP + tid] = 0.f;
        const float scl = 0.0625f;
        for (int n = tid; n < 2016; n += 128) {
            int i = (int)((127.0f - sqrtf(16129.0f - 8.0f * (float)n)) * 0.5f);
            if (i < 0) i = 0;
            if (i > 62) i = 62;
            while ((((i + 1) * (126 - i)) >> 1) <= n) ++i;
            while (((i * (127 - i)) >> 1) > n) --i;
            int j = i + 1 + (n - ((i * (127 - i)) >> 1));
            float val = v[n] * scl;
            sB[i * SBP + j] = -val;
            sB[j * SBP + i] = val;
        }
        __syncthreads();

        __nv_bfloat16* Abuf = reinterpret_cast<__nv_bfloat16*>(slot + SM_A);
        __nv_bfloat16* Bbuf = reinterpret_cast<__nv_bfloat16*>(slot + SM_B);
        const int r = tid & 63;
        const bool isA = tid < 64;
        __nv_bfloat16* dst = isA ? Abuf : Bbuf;
#pragma unroll 8
        for (int kk = 0; kk < 64; kk += 2) {
            float x0 = sB[r * SBP + kk], x1 = sB[r * SBP + kk + 1];
            if (!isA) { x0 = -x0; x1 = -x1; }
            uint32_t hw, lw;
            splitw(x0, x1, hw, lw);
            *reinterpret_cast<uint32_t*>(dst + r * LDO + kk) = hw;
            *reinterpret_cast<uint32_t*>(dst + r * LDO + 64 + kk) = lw;
        }
        __syncthreads();
    }

    float* out0 = out + (size_t)(2 * blockIdx.x) * 4096;
    float* out1 = out0 + 4096;

    float cA[2][4][4], cB[2][4][4];

    // ---- P0: mm(m0, step 0)
    mm_compute(cA, sb, wid, lid);
    __syncthreads();

    // ---- pipelined phases
#pragma unroll 1
    for (int k = 0; k < 9; k++) {
        // phase A: mm(m1, k) issued first, then epi(m0, k)
        mm_compute(cB, sb + SLOT, wid, lid);
        epi_dispatch(k, cA, smem, out0, tid, wid, lid);
        __syncthreads();
        // phase B: mm(m0, k+1) issued first (if any), then epi(m1, k)
        if (k < 8) mm_compute(cA, sb, wid, lid);
        epi_dispatch(k, cB, smem + SLOT, out1, tid, wid, lid);
        __syncthreads();
    }
}

extern "C" void kernel_launch(void* const* d_in, const int* in_sizes, int n_in,
                              void* d_out, int out_size)
{
    const float* svec = (const float*)d_in[0];
    float* out = (float*)d_out;
    const int batch = in_sizes[0] / 2016;

    cudaFuncSetAttribute(SkewSymMatrixExp_kernel,
                         cudaFuncAttributeMaxDynamicSharedMemorySize, SMEM_BYTES);
    SkewSymMatrixExp_kernel<<<batch / 2, 128, SMEM_BYTES>>>(svec, out);
}

// round 8
// speedup vs baseline: 1.6340x; 1.6340x over previous
#include <cuda_runtime.h>
#include <cuda_bf16.h>
#include <math.h>
#include <stdint.h>

// expm(S) for 4096 skew-symmetric 64x64 matrices.
// Scaling & squaring (s=4), degree-9 Paterson-Stockmeyer, 9 matmuls of 64^3.
// mma.sync.m16n8k16 bf16 split hi/lo (3 products), fp32 accumulate.
// One matrix per CTA, 4 CTAs/SM. Operands live in ONE row-major buffer:
// A-frags via ldmatrix, B-frags via ldmatrix.trans. Warps retain their own
// output quadrant as packed bf16 in registers and reuse it as A-fragments
// for the matching k-tiles of the next GEMM (halves A-side LDSM traffic).

#define LDO 136     // operand pitch in bf16 elems (272 B -> conflict-free LDSM)
#define SBP 66      // fp32 skew-matrix pitch

#define SM_X   0        // X buffer: 64 rows x [hi 64 | lo 64] bf16 -> 17408 B
#define SM_B2  17408    // B2 buffer (A operand for the PS chain)   -> 17408 B
#define SM_SB  34816    // fp32 skew matrix, pitch 66 -> 16896 B
#define SMEM_BYTES 51712

static __device__ __forceinline__ uint32_t smem_u32(const void* p) {
    uint32_t a;
    asm("{ .reg .u64 t; cvta.to.shared.u64 t, %1; cvt.u32.u64 %0, t; }" : "=r"(a) : "l"(p));
    return a;
}
static __device__ __forceinline__ void ldsm4(uint32_t* r, uint32_t a) {
    asm volatile("ldmatrix.sync.aligned.m8n8.x4.shared.b16 {%0,%1,%2,%3}, [%4];"
        : "=r"(r[0]), "=r"(r[1]), "=r"(r[2]), "=r"(r[3]) : "r"(a));
}
static __device__ __forceinline__ void ldsm4t(uint32_t* r, uint32_t a) {
    asm volatile("ldmatrix.sync.aligned.m8n8.x4.trans.shared.b16 {%0,%1,%2,%3}, [%4];"
        : "=r"(r[0]), "=r"(r[1]), "=r"(r[2]), "=r"(r[3]) : "r"(a));
}
static __device__ __forceinline__ void mma16816(float* c, const uint32_t* a, const uint32_t* b) {
    asm volatile("mma.sync.aligned.m16n8k16.row.col.f32.bf16.bf16.f32 "
        "{%0,%1,%2,%3}, {%4,%5,%6,%7}, {%8,%9}, {%0,%1,%2,%3};"
        : "+f"(c[0]), "+f"(c[1]), "+f"(c[2]), "+f"(c[3])
        : "r"(a[0]), "r"(a[1]), "r"(a[2]), "r"(a[3]), "r"(b[0]), "r"(b[1]));
}
// hw = bf16x2(x1,x0), lw = bf16x2 of residuals
static __device__ __forceinline__ void splitw(float x0, float x1, uint32_t& hw, uint32_t& lw) {
    asm("cvt.rn.bf16x2.f32 %0, %1, %2;" : "=r"(hw) : "f"(x1), "f"(x0));
    float h0 = __uint_as_float(hw << 16);
    float h1 = __uint_as_float(hw & 0xffff0000u);
    float r0 = x0 - h0, r1 = x1 - h1;
    asm("cvt.rn.bf16x2.f32 %0, %1, %2;" : "=r"(lw) : "f"(r1), "f"(r0));
}

// 3-product MMA block for one k-tile: c += Ah*Bh + Ah*Bl + Al*Bh
static __device__ __forceinline__ void prod_all(
    float c[2][4][4],
    const uint32_t* ah0, const uint32_t* ah1,
    const uint32_t* al0, const uint32_t* al1,
    uint32_t bh[2][4], uint32_t bl[2][4])
{
#pragma unroll
    for (int t = 0; t < 2; t++) {
        mma16816(c[0][2 * t],     ah0, bh[t]);
        mma16816(c[0][2 * t + 1], ah0, bh[t] + 2);
        mma16816(c[1][2 * t],     ah1, bh[t]);
        mma16816(c[1][2 * t + 1], ah1, bh[t] + 2);
        mma16816(c[0][2 * t],     ah0, bl[t]);
        mma16816(c[0][2 * t + 1], ah0, bl[t] + 2);
        mma16816(c[1][2 * t],     ah1, bl[t]);
        mma16816(c[1][2 * t + 1], ah1, bl[t] + 2);
        mma16816(c[0][2 * t],     al0, bh[t]);
        mma16816(c[0][2 * t + 1], al0, bh[t] + 2);
        mma16816(c[1][2 * t],     al1, bh[t]);
        mma16816(c[1][2 * t + 1], al1, bh[t] + 2);
    }
}

// C(64x64) = A * B. A from aBase (row-major), B from bBase (row-major, frags
// via trans ldmatrix). UK: A-frags for the warp's own k-tiles come from keep.
template <bool UK>
static __device__ __forceinline__ void mm_compute(
    float c[2][4][4], uint32_t aBase, uint32_t bBase,
    const uint32_t kH[2][2][4], const uint32_t kL[2][2][4],
    int wid, int lid)
{
#pragma unroll
    for (int m = 0; m < 2; m++)
#pragma unroll
        for (int j = 0; j < 4; j++)
#pragma unroll
            for (int q = 0; q < 4; q++) c[m][j][q] = 0.f;

    const int r0 = (wid >> 1) * 32, c0 = (wid & 1) * 32;
    const uint32_t aA = aBase + (uint32_t)((r0 + (lid & 15)) * LDO + (lid >> 4) * 8) * 2;
    const uint32_t bA = bBase
        + (uint32_t)(((lid & 7) + ((lid & 8) ? 8 : 0)) * LDO + c0 + ((lid & 16) ? 8 : 0)) * 2;
    const uint32_t rstep = 16 * LDO * 2;
    const int ownkt = c0 >> 4;   // first k-tile covered by this warp's kept quadrant

#pragma unroll
    for (int p = 0; p < 2; p++) {
        const int ktb = p ? (2 - ownkt) : ownkt;
#pragma unroll
        for (int jj = 0; jj < 2; jj++) {
            const int kt = ktb + jj;
            // B fragments (always from smem, trans)
            uint32_t bh[2][4], bl[2][4];
            const uint32_t bk = bA + (uint32_t)kt * rstep;
            ldsm4t(bh[0], bk);
            ldsm4t(bh[1], bk + 32);
            ldsm4t(bl[0], bk + 128);
            ldsm4t(bl[1], bk + 32 + 128);
            if (UK && p == 0) {
                prod_all(c, kH[0][jj], kH[1][jj], kL[0][jj], kL[1][jj], bh, bl);
            } else {
                uint32_t ah[2][4], al[2][4];
                const uint32_t ko = (uint32_t)kt * 32;
                ldsm4(ah[0], aA + ko);
                ldsm4(ah[1], aA + rstep + ko);
                ldsm4(al[0], aA + 128 + ko);
                ldsm4(al[1], aA + rstep + 128 + ko);
                prod_all(c, ah[0], ah[1], al[0], al[1], bh, bl);
            }
        }
    }
}

// Register epilogue: X[row][col] = c (+ LIN: bB*B + aI on diag).
// Writes row-major [hi|lo] into dst; WK retains own quadrant as A-frags.
template <bool WK, bool LIN, bool GM>
static __device__ __forceinline__ void epilogue(
    float c[2][4][4], __nv_bfloat16* dst, const float* sB, float* gout,
    uint32_t kH[2][2][4], uint32_t kL[2][2][4],
    int wid, int lid, float aI, float bB)
{
    const int g = lid >> 2, tg = lid & 3;
    const int r0 = (wid >> 1) * 32, c0 = (wid & 1) * 32;
#pragma unroll
    for (int m = 0; m < 2; m++) {
#pragma unroll
        for (int j = 0; j < 4; j++) {
            const int col = c0 + 8 * j + 2 * tg;
#pragma unroll
            for (int h = 0; h < 2; h++) {
                const int row = r0 + 16 * m + 8 * h + g;
                float x0 = c[m][j][2 * h], x1 = c[m][j][2 * h + 1];
                if (LIN) {
                    float2 bv = *reinterpret_cast<const float2*>(sB + row * SBP + col);
                    x0 += bB * bv.x;
                    x1 += bB * bv.y;
                    if (col == row) x0 += aI;
                    if (col + 1 == row) x1 += aI;
                }
                if (GM) {
                    *reinterpret_cast<float2*>(gout + row * 64 + col) = make_float2(x0, x1);
                } else {
                    uint32_t hw, lw;
                    splitw(x0, x1, hw, lw);
                    *reinterpret_cast<uint32_t*>(dst + row * LDO + col) = hw;
                    *reinterpret_cast<uint32_t*>(dst + row * LDO + 64 + col) = lw;
                    if (WK) {
                        kH[m][j >> 1][(j & 1) * 2 + h] = hw;
                        kL[m][j >> 1][(j & 1) * 2 + h] = lw;
                    }
                }
            }
        }
    }
}

__global__ void __launch_bounds__(128, 4)
SkewSymMatrixExp_kernel(const float* __restrict__ Svec, float* __restrict__ out)
{
    extern __shared__ char smem[];
    const uint32_t sb = smem_u32(smem);
    __nv_bfloat16* Xbuf  = reinterpret_cast<__nv_bfloat16*>(smem + SM_X);
    __nv_bfloat16* B2buf = reinterpret_cast<__nv_bfloat16*>(smem + SM_B2);
    float* sB = reinterpret_cast<float*>(smem + SM_SB);

    const int tid = threadIdx.x, wid = tid >> 5, lid = tid & 31;
    const float* v = Svec + (size_t)blockIdx.x * 2016;

    // ---- scatter S_vec into fp32 skew matrix B = S/16
    if (tid < 64) sB[tid * SBP + tid] = 0.f;
    const float scl = 0.0625f;
    for (int n = tid; n < 2016; n += 128) {
        int i = (int)((127.0f - sqrtf(16129.0f - 8.0f * (float)n)) * 0.5f);
        if (i < 0) i = 0;
        if (i > 62) i = 62;
        while ((((i + 1) * (126 - i)) >> 1) <= n) ++i;
        while (((i * (127 - i)) >> 1) > n) --i;
        int j = i + 1 + (n - ((i * (127 - i)) >> 1));
        float val = v[n] * scl;
        sB[i * SBP + j] = -val;
        sB[j * SBP + i] = val;
    }
    __syncthreads();

    // ---- initial X = split(B), row-major (A via ldsm, B via ldsm.trans)
    {
        const int r = tid >> 1;
        const int k0 = (tid & 1) * 32;
#pragma unroll 8
        for (int kk = k0; kk < k0 + 32; kk += 2) {
            float x0 = sB[r * SBP + kk], x1 = sB[r * SBP + kk + 1];
            uint32_t hw, lw;
            splitw(x0, x1, hw, lw);
            *reinterpret_cast<uint32_t*>(Xbuf + r * LDO + kk) = hw;
            *reinterpret_cast<uint32_t*>(Xbuf + r * LDO + 64 + kk) = lw;
        }
    }
    __syncthreads();

    // Taylor coeffs a_i = 1/(2i)!, b_i = 1/(2i+1)!
    const float A4 = 2.4801587e-5f, B4 = 2.7557319e-6f;
    const float A3 = 1.3888889e-3f, B3 = 1.9841270e-4f;
    const float A2 = 4.1666668e-2f, B2c = 8.3333333e-3f;
    const float A1 = 0.5f, B1 = 1.6666667e-1f;

    float c[2][4][4];
    uint32_t kH[2][2][4], kL[2][2][4];

    // ---- step 0: B2 = B*B. B2buf <- B2 (keep own quadrant). Xbuf <- r4.
    mm_compute<false>(c, sb + SM_X, sb + SM_X, kH, kL, wid, lid);
    __syncthreads();
    epilogue<true, false, false>(c, B2buf, sB, nullptr, kH, kL, wid, lid, 0.f, 0.f);
    {
        // r4 = A4*I + B4*B, row-major into Xbuf
        const int r = tid >> 1;
        const int k0 = (tid & 1) * 32;
#pragma unroll 8
        for (int kk = k0; kk < k0 + 32; kk += 2) {
            float x0 = B4 * sB[r * SBP + kk] + (kk == r ? A4 : 0.f);
            float x1 = B4 * sB[r * SBP + kk + 1] + (kk + 1 == r ? A4 : 0.f);
            uint32_t hw, lw;
            splitw(x0, x1, hw, lw);
            *reinterpret_cast<uint32_t*>(Xbuf + r * LDO + kk) = hw;
            *reinterpret_cast<uint32_t*>(Xbuf + r * LDO + 64 + kk) = lw;
        }
    }
    __syncthreads();

    // ---- chain steps 1..3: r <- a I + b B + B2*r   (A = B2 via keep, B = Xbuf)
    const float av[3] = { A3, A2, A1 };
    const float bv[3] = { B3, B2c, B1 };
#pragma unroll 1
    for (int s = 0; s < 3; s++) {
        mm_compute<true>(c, sb + SM_B2, sb + SM_X, kH, kL, wid, lid);
        __syncthreads();
        epilogue<false, true, false>(c, Xbuf, sB, nullptr, kH, kL, wid, lid, av[s], bv[s]);
        __syncthreads();
    }

    // ---- step 4: P = I + B + B2*r1. Xbuf <- P, keep <- P quadrant.
    mm_compute<true>(c, sb + SM_B2, sb + SM_X, kH, kL, wid, lid);
    __syncthreads();
    epilogue<true, true, false>(c, Xbuf, sB, nullptr, kH, kL, wid, lid, 1.f, 1.f);
    __syncthreads();

    // ---- squarings 1..3: X <- X*X (A own-kt from keep, B via trans)
#pragma unroll 1
    for (int s = 0; s < 3; s++) {
        mm_compute<true>(c, sb + SM_X, sb + SM_X, kH, kL, wid, lid);
        __syncthreads();
        epilogue<true, false, false>(c, Xbuf, sB, nullptr, kH, kL, wid, lid, 0.f, 0.f);
        __syncthreads();
    }

    // ---- squaring 4: straight to global
    mm_compute<true>(c, sb + SM_X, sb + SM_X, kH, kL, wid, lid);
    epilogue<false, false, true>(c, Xbuf, sB, out + (size_t)blockIdx.x * 4096,
                                 kH, kL, wid, lid, 0.f, 0.f);
}

extern "C" void kernel_launch(void* const* d_in, const int* in_sizes, int n_in,
                              void* d_out, int out_size)
{
    const float* svec = (const float*)d_in[0];
    float* out = (float*)d_out;
    const int batch = in_sizes[0] / 2016;

    cudaFuncSetAttribute(SkewSymMatrixExp_kernel,
                         cudaFuncAttributeMaxDynamicSharedMemorySize, SMEM_BYTES);
    SkewSymMatrixExp_kernel<<<batch, 128, SMEM_BYTES>>>(svec, out);
}